// round 13
// baseline (speedup 1.0000x reference)
#include <cuda_runtime.h>
#include <math.h>
#include <stdint.h>

// ---- problem dims ----
#define Tn 4096      // B*S tokens
#define Dn 768
#define Hn 12
#define DHn 64
#define Sn 512
#define Bsz 8
#define En 8
#define Fn 3072
#define TOPK 2

#define BM 128
#define BN 128
#define BK 32
#define LDA 36     // A smem row stride (words); 36r mod 32 = 4r -> ldmatrix rows cover all banks
#define LDB 136    // B smem row stride (words); 8c+g is a bank permutation
#define A_ST (BM * LDA)            // 4608 words per stage
#define B_ST (BK * LDB)            // 4352 words per stage
#define NSTAGE 3
#define SMEM_SZ (NSTAGE * (A_ST + B_ST) * 4)   // 107,520 bytes

// ---- scratch (device globals: allocation-free per harness rules) ----
__device__ float g_h1[Tn * Dn];
__device__ float g_q[Tn * Dn];
__device__ float g_k[Tn * Dn];
__device__ float g_v[Tn * Dn];
__device__ float g_att[Tn * Dn];
__device__ float g_x1[Tn * Dn];
__device__ float g_h2r[Tn * Dn];                  // tf32-rounded (GEMM A)
__device__ float g_h2x[Tn * Dn];                  // exact (routing)
__device__ float g_mid[(size_t)Tn * TOPK * Fn];   // ~100 MB
__device__ float g_eout[Tn * TOPK * Dn];          // ~25 MB
// tf32-rounded weight copies
__device__ float g_wqr[Dn * Dn];
__device__ float g_wkr[Dn * Dn];
__device__ float g_wvr[Dn * Dn];
__device__ float g_wor[Dn * Dn];
__device__ float g_w1r[(size_t)En * Dn * Fn];     // 72 MB
__device__ float g_w2r[(size_t)En * Fn * Dn];     // 72 MB
__device__ int   g_idx[Tn * TOPK];
__device__ float g_gate[Tn * TOPK];
__device__ int   g_pos[Tn * TOPK];
__device__ int   g_slotof[Tn * TOPK];
__device__ int   g_slot2tok[Tn * TOPK];
__device__ int   g_counts[En];
__device__ int   g_offsets[En];

// ---- helpers ----
__device__ __forceinline__ float gelu_tanh(float x) {
    const float c = 0.7978845608028654f;   // sqrt(2/pi)
    float t = tanhf(c * (x + 0.044715f * x * x * x));
    return 0.5f * x * (1.0f + t);
}

__device__ __forceinline__ uint32_t f2tf(float x) {
    uint32_t r;
    asm("cvt.rna.tf32.f32 %0, %1;" : "=r"(r) : "f"(x));
    return r;
}
__device__ __forceinline__ float roundtf(float x) { return __uint_as_float(f2tf(x)); }

__device__ __forceinline__ void mma_tf32(float* cc,
    uint32_t a0, uint32_t a1, uint32_t a2, uint32_t a3,
    uint32_t b0, uint32_t b1) {
    asm volatile(
        "mma.sync.aligned.m16n8k8.row.col.f32.tf32.tf32.f32 "
        "{%0,%1,%2,%3},{%4,%5,%6,%7},{%8,%9},{%0,%1,%2,%3};"
        : "+f"(cc[0]), "+f"(cc[1]), "+f"(cc[2]), "+f"(cc[3])
        : "r"(a0), "r"(a1), "r"(a2), "r"(a3), "r"(b0), "r"(b1));
}

// ldmatrix x4: four 8x8 b16 tiles == four 8x4 b32 tiles; b32 fragment map
// (row=lane/4, col=lane%4) == m16n8k8.tf32 A fragment.
__device__ __forceinline__ void ldsm_x4(uint32_t& r0, uint32_t& r1,
                                        uint32_t& r2, uint32_t& r3, uint32_t addr) {
    asm volatile("ldmatrix.sync.aligned.m8n8.x4.shared.b16 {%0,%1,%2,%3}, [%4];"
                 : "=r"(r0), "=r"(r1), "=r"(r2), "=r"(r3) : "r"(addr));
}

__device__ __forceinline__ uint32_t sptr(const void* p) {
    return (uint32_t)__cvta_generic_to_shared(p);
}
#define CP16(s, g) asm volatile("cp.async.cg.shared.global [%0], [%1], 16;" :: "r"(s), "l"(g))
#define CPCOMMIT() asm volatile("cp.async.commit_group;")
#define CPWAIT1()  asm volatile("cp.async.wait_group 1;")
#define CPWAIT0()  asm volatile("cp.async.wait_group 0;")

// ---------------------------------------------------------------------------
// tf32 tensor-core GEMM core: 128x128 tile, BK=32, 256 threads (8 warps),
// warp tile 64x32, fp32 accumulate. 3-stage cp.async ring, ONE barrier/tile.
// Per iteration it: wait(own group it) -> barrier (all warps done with it-1,
// data of it visible) -> issue stage (it+2)%3 (buffer consumed at it-1: safe)
// -> compute stage it%3.
// Smem per stage: A [128][LDA] row-major [m][k]; B [32][LDB] [k][n].
// Staging (per thread/tile): A row t>>1, 16 cols at (t&1)*16 (4x cp16);
//                            B row t>>3, 16 cols at (t&7)*16 (4x cp16).
// Compute: A = ldmatrix.x4 per (mf,kb) [16/tile]; B = 2 scalar LDS per (nf,kb).
// ---------------------------------------------------------------------------
__device__ __forceinline__ void gemm_core(
    const float* __restrict__ aptr,   // A + (bm + ar)*lda_glob + akc
    const float* __restrict__ bptr,   // B + bkr*ldb + bn + bnc
    int ldb, int iters,
    float (&acc)[16][4],
    float* __restrict__ sm,
    int lane, int m0base, int n0base,
    int ar, int akc, int bkr, int bnc)
{
    float* Ab = sm;
    float* Bb = sm + NSTAGE * A_ST;
    int g = lane >> 2, c = lane & 3;

    uint32_t aS = sptr(Ab + ar * LDA + akc);
    uint32_t bS = sptr(Bb + bkr * LDB + bnc);
    int lrow = ((lane >> 3) & 1) * 8 + (lane & 7);
    int lcol = (lane >> 4) * 4;
    uint32_t aL = sptr(Ab + (m0base + lrow) * LDA + lcol);
    const uint32_t ASB = A_ST * 4;
    const uint32_t BSB = B_ST * 4;

#define ISSUE(s, it_) do {                                              \
    const float* _ag = aptr + (it_) * BK;                               \
    uint32_t _as = aS + (uint32_t)(s) * ASB;                            \
    CP16(_as, _ag); CP16(_as + 16, _ag + 4);                            \
    CP16(_as + 32, _ag + 8); CP16(_as + 48, _ag + 12);                  \
    const float* _bg = bptr + (size_t)(it_) * BK * ldb;                 \
    uint32_t _bs = bS + (uint32_t)(s) * BSB;                            \
    CP16(_bs, _bg); CP16(_bs + 16, _bg + 4);                            \
    CP16(_bs + 32, _bg + 8); CP16(_bs + 48, _bg + 12);                  \
    CPCOMMIT(); } while (0)

    ISSUE(0, 0);
    ISSUE(1, 1);

    int st = 0;
    for (int it = 0; it < iters; it++) {
        if (it + 1 < iters) CPWAIT1(); else CPWAIT0();
        __syncthreads();
        if (it + 2 < iters) {
            int sn = st + 2; if (sn >= NSTAGE) sn -= NSTAGE;
            ISSUE(sn, it + 2);
        }
        const float* Bst = Bb + st * B_ST;
        uint32_t aLs = aL + (uint32_t)st * ASB;
        #pragma unroll
        for (int kb = 0; kb < 4; kb++) {
            uint32_t bf[4][2];
            #pragma unroll
            for (int nf = 0; nf < 4; nf++) {
                int n0 = n0base + nf * 8 + g;
                bf[nf][0] = __float_as_uint(Bst[(kb * 8 + c) * LDB + n0]);
                bf[nf][1] = __float_as_uint(Bst[(kb * 8 + c + 4) * LDB + n0]);
            }
            #pragma unroll
            for (int mf = 0; mf < 4; mf++) {
                uint32_t fa0, fa1, fa2, fa3;
                ldsm_x4(fa0, fa1, fa2, fa3,
                        aLs + (uint32_t)(mf * 16 * LDA * 4 + kb * 32));
                #pragma unroll
                for (int nf = 0; nf < 4; nf++)
                    mma_tf32(acc[mf * 4 + nf], fa0, fa1, fa2, fa3,
                             bf[nf][0], bf[nf][1]);
            }
        }
        if (++st == NSTAGE) st = 0;
    }
#undef ISSUE
}

#define MMA_PROLOG()                              \
    int t    = threadIdx.x;                       \
    int lane = t & 31;                            \
    int wid  = t >> 5;                            \
    int ar   = t >> 1;                            \
    int akc  = (t & 1) * 16;                      \
    int bkr  = t >> 3;                            \
    int bnc  = (t & 7) * 16;                      \
    int g    = lane >> 2;                         \
    int c    = lane & 3;                          \
    int m0base = (wid & 1) * 64;                  \
    int n0base = (wid >> 1) * 32;                 \
    extern __shared__ float smx[];                \
    float acc[16][4];                             \
    _Pragma("unroll")                             \
    for (int _i = 0; _i < 16; _i++)               \
        for (int _j = 0; _j < 4; _j++) acc[_i][_j] = 0.f;

// ---------------------------------------------------------------------------
// Weight tf32 pre-round (fused): small = 4 DxD weights, big = w1 + w2
// ---------------------------------------------------------------------------
__global__ void round_small(const float* __restrict__ wq, const float* __restrict__ wk,
                            const float* __restrict__ wv, const float* __restrict__ wo) {
    const float* in = (blockIdx.y == 0) ? wq : (blockIdx.y == 1) ? wk
                    : (blockIdx.y == 2) ? wv : wo;
    float* outp = (blockIdx.y == 0) ? g_wqr : (blockIdx.y == 1) ? g_wkr
                : (blockIdx.y == 2) ? g_wvr : g_wor;
    int i = blockIdx.x * 256 + threadIdx.x;
    float4 v = ((const float4*)in)[i];
    v.x = roundtf(v.x); v.y = roundtf(v.y); v.z = roundtf(v.z); v.w = roundtf(v.w);
    ((float4*)outp)[i] = v;
}

__global__ void round_big(const float* __restrict__ w1, const float* __restrict__ w2) {
    const float* in = (blockIdx.y == 0) ? w1 : w2;
    float* outp = (blockIdx.y == 0) ? g_w1r : g_w2r;
    size_t i = (size_t)blockIdx.x * 256 + threadIdx.x;
    float4 v = ((const float4*)in)[i];
    v.x = roundtf(v.x); v.y = roundtf(v.y); v.z = roundtf(v.z); v.w = roundtf(v.w);
    ((float4*)outp)[i] = v;
}

// ---------------------------------------------------------------------------
// Fused QKV projection: grid (Tn/128, Dn/128, 3)
// ---------------------------------------------------------------------------
__global__ void __launch_bounds__(256, 2)
qkv_gemm(const float* __restrict__ h1) {
    const float* W = (blockIdx.z == 0) ? g_wqr : (blockIdx.z == 1) ? g_wkr : g_wvr;
    float* C = (blockIdx.z == 0) ? g_q : (blockIdx.z == 1) ? g_k : g_v;
    int bm = blockIdx.x * BM, bn = blockIdx.y * BN;
    MMA_PROLOG();
    gemm_core(h1 + (size_t)(bm + ar) * Dn + akc,
              W + (size_t)bkr * Dn + bn + bnc,
              Dn, Dn / BK, acc, smx, lane, m0base, n0base, ar, akc, bkr, bnc);
    #pragma unroll
    for (int mf = 0; mf < 4; mf++) {
        int r0 = bm + m0base + mf * 16 + g;
        #pragma unroll
        for (int nf = 0; nf < 4; nf++) {
            int cb = bn + n0base + nf * 8 + c * 2;
            float* cc = acc[mf * 4 + nf];
            *(float2*)(C + (size_t)r0 * Dn + cb)       = make_float2(cc[0], cc[1]);
            *(float2*)(C + (size_t)(r0 + 8) * Dn + cb) = make_float2(cc[2], cc[3]);
        }
    }
}

// ---------------------------------------------------------------------------
// O projection + residual: x1 = x + att @ wo.  grid (Tn/128, Dn/128)
// ---------------------------------------------------------------------------
__global__ void __launch_bounds__(256, 2)
oproj_gemm(const float* __restrict__ x) {
    int bm = blockIdx.x * BM, bn = blockIdx.y * BN;
    MMA_PROLOG();
    gemm_core(g_att + (size_t)(bm + ar) * Dn + akc,
              g_wor + (size_t)bkr * Dn + bn + bnc,
              Dn, Dn / BK, acc, smx, lane, m0base, n0base, ar, akc, bkr, bnc);
    #pragma unroll
    for (int mf = 0; mf < 4; mf++) {
        int r0 = bm + m0base + mf * 16 + g;
        #pragma unroll
        for (int nf = 0; nf < 4; nf++) {
            int cb = bn + n0base + nf * 8 + c * 2;
            float* cc = acc[mf * 4 + nf];
            size_t p0 = (size_t)r0 * Dn + cb;
            size_t p1 = (size_t)(r0 + 8) * Dn + cb;
            float2 x0 = *(const float2*)(x + p0);
            float2 x1v = *(const float2*)(x + p1);
            *(float2*)(g_x1 + p0) = make_float2(x0.x + cc[0], x0.y + cc[1]);
            *(float2*)(g_x1 + p1) = make_float2(x1v.x + cc[2], x1v.y + cc[3]);
        }
    }
}

// ---------------------------------------------------------------------------
// MoE FFN1: gathered rows, gelu(X@w1[e] + b1[e]) -> g_mid (tf32-rounded)
// grid (Tn/128, Fn/128, E)
// ---------------------------------------------------------------------------
__global__ void __launch_bounds__(256, 2)
moe_ffn1(const float* __restrict__ b1) {
    int e = blockIdx.z;
    int cnt = g_counts[e];
    int bm = blockIdx.x * BM;
    if (bm >= cnt) return;
    int off = g_offsets[e];
    int bn = blockIdx.y * BN;
    MMA_PROLOG();
    int arow = bm + ar; if (arow >= cnt) arow = cnt - 1;
    int tok = g_slot2tok[off + arow];
    gemm_core(g_h2r + (size_t)tok * Dn + akc,
              g_w1r + (size_t)e * Dn * Fn + (size_t)bkr * Fn + bn + bnc,
              Fn, Dn / BK, acc, smx, lane, m0base, n0base, ar, akc, bkr, bnc);
    #pragma unroll
    for (int mf = 0; mf < 4; mf++) {
        int r0 = bm + m0base + mf * 16 + g;
        int r1 = r0 + 8;
        #pragma unroll
        for (int nf = 0; nf < 4; nf++) {
            int cb = bn + n0base + nf * 8 + c * 2;
            float bv0 = b1[e * Fn + cb], bv1 = b1[e * Fn + cb + 1];
            float* cc = acc[mf * 4 + nf];
            if (r0 < cnt)
                *(float2*)(g_mid + (size_t)(off + r0) * Fn + cb) =
                    make_float2(roundtf(gelu_tanh(cc[0] + bv0)),
                                roundtf(gelu_tanh(cc[1] + bv1)));
            if (r1 < cnt)
                *(float2*)(g_mid + (size_t)(off + r1) * Fn + cb) =
                    make_float2(roundtf(gelu_tanh(cc[2] + bv0)),
                                roundtf(gelu_tanh(cc[3] + bv1)));
        }
    }
}

// ---------------------------------------------------------------------------
// MoE FFN2: mid@w2[e] + b2[e] -> g_eout.  grid (Tn/128, Dn/128, E)
// ---------------------------------------------------------------------------
__global__ void __launch_bounds__(256, 2)
moe_ffn2(const float* __restrict__ b2) {
    int e = blockIdx.z;
    int cnt = g_counts[e];
    int bm = blockIdx.x * BM;
    if (bm >= cnt) return;
    int off = g_offsets[e];
    int bn = blockIdx.y * BN;
    MMA_PROLOG();
    int arow = bm + ar; if (arow >= cnt) arow = cnt - 1;
    gemm_core(g_mid + (size_t)(off + arow) * Fn + akc,
              g_w2r + (size_t)e * Fn * Dn + (size_t)bkr * Dn + bn + bnc,
              Dn, Fn / BK, acc, smx, lane, m0base, n0base, ar, akc, bkr, bnc);
    #pragma unroll
    for (int mf = 0; mf < 4; mf++) {
        int r0 = bm + m0base + mf * 16 + g;
        int r1 = r0 + 8;
        #pragma unroll
        for (int nf = 0; nf < 4; nf++) {
            int cb = bn + n0base + nf * 8 + c * 2;
            float bv0 = b2[e * Dn + cb], bv1 = b2[e * Dn + cb + 1];
            float* cc = acc[mf * 4 + nf];
            if (r0 < cnt)
                *(float2*)(g_eout + (size_t)(off + r0) * Dn + cb) =
                    make_float2(cc[0] + bv0, cc[1] + bv1);
            if (r1 < cnt)
                *(float2*)(g_eout + (size_t)(off + r1) * Dn + cb) =
                    make_float2(cc[2] + bv0, cc[3] + bv1);
        }
    }
}

// ---------------------------------------------------------------------------
// LayerNorm: one block per token, 256 threads, D=768 (3 elems/thread).
// out = tf32-rounded LN (feeds GEMM A); out2 (optional) = exact LN (routing).
// ---------------------------------------------------------------------------
__global__ void ln_kernel(const float* __restrict__ x,
                          const float* __restrict__ g,
                          const float* __restrict__ b,
                          float* __restrict__ out,
                          float* __restrict__ out2) {
    int t = blockIdx.x;
    const float* row = x + (size_t)t * Dn;
    int tid = threadIdx.x;
    float v0 = row[tid], v1 = row[tid + 256], v2 = row[tid + 512];
    float s  = v0 + v1 + v2;
    float ss = v0 * v0 + v1 * v1 + v2 * v2;
    #pragma unroll
    for (int o = 16; o; o >>= 1) {
        s  += __shfl_down_sync(0xffffffffu, s, o);
        ss += __shfl_down_sync(0xffffffffu, ss, o);
    }
    __shared__ float rs[8], rss[8];
    __shared__ float mu_s, rstd_s;
    int w = tid >> 5, l = tid & 31;
    if (l == 0) { rs[w] = s; rss[w] = ss; }
    __syncthreads();
    if (tid == 0) {
        float S = 0.f, SS = 0.f;
        #pragma unroll
        for (int i = 0; i < 8; i++) { S += rs[i]; SS += rss[i]; }
        float mu  = S / (float)Dn;
        float var = SS / (float)Dn - mu * mu;
        mu_s = mu; rstd_s = rsqrtf(var + 1e-5f);
    }
    __syncthreads();
    float mu = mu_s, rstd = rstd_s;
    float* orow = out + (size_t)t * Dn;
    float e0 = (v0 - mu) * rstd * g[tid]       + b[tid];
    float e1 = (v1 - mu) * rstd * g[tid + 256] + b[tid + 256];
    float e2 = (v2 - mu) * rstd * g[tid + 512] + b[tid + 512];
    orow[tid]       = roundtf(e0);
    orow[tid + 256] = roundtf(e1);
    orow[tid + 512] = roundtf(e2);
    if (out2) {
        float* xrow = out2 + (size_t)t * Dn;
        xrow[tid] = e0; xrow[tid + 256] = e1; xrow[tid + 512] = e2;
    }
}

// ---------------------------------------------------------------------------
// Flash-style attention: grid (S/128, H, B), 128 threads; one thread = one q row.
// Output tf32-rounded (feeds oproj A).
// ---------------------------------------------------------------------------
__global__ void __launch_bounds__(128)
attn_kernel(const float* __restrict__ q, const float* __restrict__ k,
            const float* __restrict__ v, float* __restrict__ o_out) {
    const int KT = 32;
    int h = blockIdx.y, b = blockIdx.z;
    int tid = threadIdx.x;
    int qrow = b * Sn + blockIdx.x * 128 + tid;
    const float* qptr = q + (size_t)qrow * Dn + h * DHn;
    float qreg[64];
    #pragma unroll
    for (int d = 0; d < 64; d++) qreg[d] = qptr[d] * 0.125f;  // 1/sqrt(64)
    float oacc[64];
    #pragma unroll
    for (int d = 0; d < 64; d++) oacc[d] = 0.f;
    float m = -1e30f, lsum = 0.f;

    __shared__ float Ks[KT][64], Vs[KT][64];
    for (int k0 = 0; k0 < Sn; k0 += KT) {
        for (int i = tid; i < KT * 64; i += 128) {
            int r = i >> 6, ccol = i & 63;
            size_t src = (size_t)(b * Sn + k0 + r) * Dn + h * DHn + ccol;
            Ks[r][ccol] = k[src];
            Vs[r][ccol] = v[src];
        }
        __syncthreads();
        float sv[KT];
        float smax = -1e30f;
        #pragma unroll
        for (int j = 0; j < KT; j++) {
            float s = 0.f;
            #pragma unroll
            for (int d = 0; d < 64; d++) s += qreg[d] * Ks[j][d];
            sv[j] = s;
            smax = fmaxf(smax, s);
        }
        float mnew = fmaxf(m, smax);
        float alpha = expf(m - mnew);
        float psum = 0.f;
        #pragma unroll
        for (int j = 0; j < KT; j++) { float p = expf(sv[j] - mnew); sv[j] = p; psum += p; }
        lsum = lsum * alpha + psum;
        #pragma unroll
        for (int d = 0; d < 64; d++) {
            float a = 0.f;
            #pragma unroll
            for (int j = 0; j < KT; j++) a += sv[j] * Vs[j][d];
            oacc[d] = oacc[d] * alpha + a;
        }
        m = mnew;
        __syncthreads();
    }
    float inv = 1.0f / lsum;
    float* op = o_out + (size_t)qrow * Dn + h * DHn;
    #pragma unroll
    for (int d = 0; d < 64; d++) op[d] = roundtf(oacc[d] * inv);
}

// ---------------------------------------------------------------------------
// MoE routing (reads EXACT h2 + exact gate_w: selection identical to reference)
// ---------------------------------------------------------------------------
__global__ void zero_counts_kernel() {
    if (threadIdx.x < En) g_counts[threadIdx.x] = 0;
}

__global__ void routing_kernel(const float* __restrict__ h2,
                               const float* __restrict__ gate_w,
                               const float* __restrict__ gate_b,
                               const float* __restrict__ bias_e) {
    int t = blockIdx.x;
    int wid = threadIdx.x >> 5, lane = threadIdx.x & 31;
    __shared__ float logit[En];
    float s = 0.f;
    const float* row = h2 + (size_t)t * Dn;
    for (int d = lane; d < Dn; d += 32) s += row[d] * gate_w[d * En + wid];
    #pragma unroll
    for (int o = 16; o; o >>= 1) s += __shfl_down_sync(0xffffffffu, s, o);
    if (lane == 0) logit[wid] = s + gate_b[wid];   // TAU = 1
    __syncthreads();
    if (threadIdx.x == 0) {
        float sel[En];
        #pragma unroll
        for (int e = 0; e < En; e++) sel[e] = logit[e] + bias_e[e];
        int i0 = 0;
        #pragma unroll
        for (int e = 1; e < En; e++) if (sel[e] > sel[i0]) i0 = e;
        int i1 = (i0 == 0) ? 1 : 0;
        #pragma unroll
        for (int e = 0; e < En; e++) if (e != i0 && sel[e] > sel[i1]) i1 = e;
        float l0 = logit[i0], l1 = logit[i1];
        float mm = fmaxf(l0, l1);
        float e0 = expf(l0 - mm), e1 = expf(l1 - mm);
        float inv = 1.0f / (e0 + e1);
        g_idx[t * 2] = i0;     g_idx[t * 2 + 1] = i1;
        g_gate[t * 2] = e0 * inv; g_gate[t * 2 + 1] = e1 * inv;
        g_pos[t * 2]     = atomicAdd(&g_counts[i0], 1);
        g_pos[t * 2 + 1] = atomicAdd(&g_counts[i1], 1);
    }
}

__global__ void offsets_kernel() {
    if (threadIdx.x == 0) {
        int acc = 0;
        for (int e = 0; e < En; e++) { g_offsets[e] = acc; acc += g_counts[e]; }
    }
}

__global__ void fill_slots_kernel() {
    int t = blockIdx.x * 256 + threadIdx.x;
    if (t >= Tn) return;
    #pragma unroll
    for (int kk = 0; kk < 2; kk++) {
        int e = g_idx[t * 2 + kk];
        int slot = g_offsets[e] + g_pos[t * 2 + kk];
        g_slotof[t * 2 + kk] = slot;
        g_slot2tok[slot] = t;
    }
}

// ---------------------------------------------------------------------------
// Final combine: out = x1 + g0*eout[slot0] + g1*eout[slot1]
// ---------------------------------------------------------------------------
__global__ void combine_kernel(const float* __restrict__ x1, float* __restrict__ out) {
    int t = blockIdx.x;
    int d = blockIdx.y * 256 + threadIdx.x;
    int s0 = g_slotof[t * 2], s1 = g_slotof[t * 2 + 1];
    float g0 = g_gate[t * 2], g1 = g_gate[t * 2 + 1];
    out[(size_t)t * Dn + d] = x1[(size_t)t * Dn + d]
                            + g0 * g_eout[(size_t)s0 * Dn + d]
                            + g1 * g_eout[(size_t)s1 * Dn + d];
}

// ---------------------------------------------------------------------------
// launch
// ---------------------------------------------------------------------------
extern "C" void kernel_launch(void* const* d_in, const int* in_sizes, int n_in,
                              void* d_out, int out_size) {
    const float* x      = (const float*)d_in[0];
    const float* wq     = (const float*)d_in[1];
    const float* wk     = (const float*)d_in[2];
    const float* wv     = (const float*)d_in[3];
    const float* wo     = (const float*)d_in[4];
    const float* ln1_g  = (const float*)d_in[5];
    const float* ln1_b  = (const float*)d_in[6];
    const float* ln2_g  = (const float*)d_in[7];
    const float* ln2_b  = (const float*)d_in[8];
    const float* gate_w = (const float*)d_in[9];
    const float* gate_b = (const float*)d_in[10];
    const float* bias_e = (const float*)d_in[11];
    const float* w1     = (const float*)d_in[12];
    const float* b1     = (const float*)d_in[13];
    const float* w2     = (const float*)d_in[14];
    const float* b2     = (const float*)d_in[15];
    float* out = (float*)d_out;

    float *h1, *qb, *kb, *vb, *att, *x1, *h2r, *h2x;
    cudaGetSymbolAddress((void**)&h1,  g_h1);
    cudaGetSymbolAddress((void**)&qb,  g_q);
    cudaGetSymbolAddress((void**)&kb,  g_k);
    cudaGetSymbolAddress((void**)&vb,  g_v);
    cudaGetSymbolAddress((void**)&att, g_att);
    cudaGetSymbolAddress((void**)&x1,  g_x1);
    cudaGetSymbolAddress((void**)&h2r, g_h2r);
    cudaGetSymbolAddress((void**)&h2x, g_h2x);

    // raise dynamic smem limits (idempotent; host-side attribute, capture-safe)
    static int smem_set = 0;
    if (!smem_set) {
        cudaFuncSetAttribute(qkv_gemm,  cudaFuncAttributeMaxDynamicSharedMemorySize, SMEM_SZ);
        cudaFuncSetAttribute(oproj_gemm, cudaFuncAttributeMaxDynamicSharedMemorySize, SMEM_SZ);
        cudaFuncSetAttribute(moe_ffn1,  cudaFuncAttributeMaxDynamicSharedMemorySize, SMEM_SZ);
        cudaFuncSetAttribute(moe_ffn2,  cudaFuncAttributeMaxDynamicSharedMemorySize, SMEM_SZ);
        smem_set = 1;
    }

    // --- tf32 pre-round of weights (2 fused launches) ---
    const int DD4 = Dn * Dn / 4;                  // 147456
    const int W4  = En * Dn * Fn / 4;             // 4718592
    round_small<<<dim3(DD4 / 256, 4), 256>>>(wq, wk, wv, wo);
    round_big<<<dim3(W4 / 256, 2), 256>>>(w1, w2);

    // --- attention block ---
    ln_kernel<<<Tn, 256>>>(x, ln1_g, ln1_b, h1, nullptr);
    qkv_gemm<<<dim3(Tn / BM, Dn / BN, 3), 256, SMEM_SZ>>>(h1);
    attn_kernel<<<dim3(Sn / 128, Hn, Bsz), 128>>>(qb, kb, vb, att);
    oproj_gemm<<<dim3(Tn / BM, Dn / BN), 256, SMEM_SZ>>>(x);

    // --- MoE block ---
    ln_kernel<<<Tn, 256>>>(x1, ln2_g, ln2_b, h2r, h2x);
    zero_counts_kernel<<<1, 32>>>();
    routing_kernel<<<Tn, 256>>>(h2x, gate_w, gate_b, bias_e);
    offsets_kernel<<<1, 32>>>();
    fill_slots_kernel<<<Tn / 256, 256>>>();
    moe_ffn1<<<dim3(Tn / BM, Fn / BN, En), 256, SMEM_SZ>>>(b1);
    moe_ffn2<<<dim3(Tn / BM, Dn / BN, En), 256, SMEM_SZ>>>(b2);
    combine_kernel<<<dim3(Tn, Dn / 256), 256>>>(x1, out);
}

// round 14
// speedup vs baseline: 1.0657x; 1.0657x over previous
#include <cuda_runtime.h>
#include <math.h>
#include <stdint.h>

// ---- problem dims ----
#define Tn 4096      // B*S tokens
#define Dn 768
#define Hn 12
#define DHn 64
#define Sn 512
#define Bsz 8
#define En 8
#define Fn 3072
#define TOPK 2

#define BM 128
#define BN 128

// ---- core16 (round-12, for MoE FFN): BK=16, 2-stage, static smem ----
#define BK16 16
#define LDA16 20   // A row stride (words)
#define LDB16 136  // B row stride (words)

// ---- core32 (round-13, for dense proj): BK=32, 3-stage ring, dynamic smem ----
#define BK32 32
#define LDA32 36
#define LDB32 136
#define A_ST (BM * LDA32)           // 4608 words/stage
#define B_ST (BK32 * LDB32)         // 4352 words/stage
#define NSTAGE 3
#define SMEM_SZ (NSTAGE * (A_ST + B_ST) * 4)   // 107,520 bytes

// ---- scratch (device globals: allocation-free per harness rules) ----
__device__ float g_h1[Tn * Dn];
__device__ float g_q[Tn * Dn];
__device__ float g_k[Tn * Dn];
__device__ float g_v[Tn * Dn];
__device__ float g_att[Tn * Dn];
__device__ float g_x1[Tn * Dn];
__device__ float g_h2r[Tn * Dn];                  // tf32-rounded (GEMM A)
__device__ float g_h2x[Tn * Dn];                  // exact (routing)
__device__ float g_mid[(size_t)Tn * TOPK * Fn];   // ~100 MB
__device__ float g_eout[Tn * TOPK * Dn];          // ~25 MB
// tf32-rounded weight copies
__device__ float g_wqr[Dn * Dn];
__device__ float g_wkr[Dn * Dn];
__device__ float g_wvr[Dn * Dn];
__device__ float g_wor[Dn * Dn];
__device__ float g_w1r[(size_t)En * Dn * Fn];     // 72 MB
__device__ float g_w2r[(size_t)En * Fn * Dn];     // 72 MB
__device__ int   g_idx[Tn * TOPK];
__device__ float g_gate[Tn * TOPK];
__device__ int   g_pos[Tn * TOPK];
__device__ int   g_slotof[Tn * TOPK];
__device__ int   g_slot2tok[Tn * TOPK];
__device__ int   g_counts[En];
__device__ int   g_offsets[En];

// ---- helpers ----
__device__ __forceinline__ float gelu_tanh(float x) {
    const float c = 0.7978845608028654f;   // sqrt(2/pi)
    float t = tanhf(c * (x + 0.044715f * x * x * x));
    return 0.5f * x * (1.0f + t);
}

__device__ __forceinline__ uint32_t f2tf(float x) {
    uint32_t r;
    asm("cvt.rna.tf32.f32 %0, %1;" : "=r"(r) : "f"(x));
    return r;
}
__device__ __forceinline__ float roundtf(float x) { return __uint_as_float(f2tf(x)); }

__device__ __forceinline__ void mma_tf32(float* cc,
    uint32_t a0, uint32_t a1, uint32_t a2, uint32_t a3,
    uint32_t b0, uint32_t b1) {
    asm volatile(
        "mma.sync.aligned.m16n8k8.row.col.f32.tf32.tf32.f32 "
        "{%0,%1,%2,%3},{%4,%5,%6,%7},{%8,%9},{%0,%1,%2,%3};"
        : "+f"(cc[0]), "+f"(cc[1]), "+f"(cc[2]), "+f"(cc[3])
        : "r"(a0), "r"(a1), "r"(a2), "r"(a3), "r"(b0), "r"(b1));
}

// ldmatrix x4: four 8x8 b16 tiles == four 8x4 b32 tiles; b32 fragment map
// (row=lane/4, col=lane%4) == m16n8k8.tf32 A fragment.
__device__ __forceinline__ void ldsm_x4(uint32_t& r0, uint32_t& r1,
                                        uint32_t& r2, uint32_t& r3, uint32_t addr) {
    asm volatile("ldmatrix.sync.aligned.m8n8.x4.shared.b16 {%0,%1,%2,%3}, [%4];"
                 : "=r"(r0), "=r"(r1), "=r"(r2), "=r"(r3) : "r"(addr));
}

__device__ __forceinline__ uint32_t sptr(const void* p) {
    return (uint32_t)__cvta_generic_to_shared(p);
}
#define CP16(s, g) asm volatile("cp.async.cg.shared.global [%0], [%1], 16;" :: "r"(s), "l"(g))
#define CPCOMMIT() asm volatile("cp.async.commit_group;")
#define CPWAIT1()  asm volatile("cp.async.wait_group 1;")
#define CPWAIT0()  asm volatile("cp.async.wait_group 0;")

// ===========================================================================
// core16: round-12 GEMM core (BK=16, 2-stage, 2 barriers/tile, static smem).
// Used by moe_ffn1 / moe_ffn2 (best measured config for the MoE path).
// ===========================================================================
__device__ __forceinline__ void gemm_core16(
    const float* __restrict__ arow,   // A base + (staging row)*lda (+0 col)
    const float* __restrict__ bcol,   // B base + bn + bc
    int ldb, int iters,
    float (&acc)[16][4],
    float (*As)[BM][LDA16], float (*Bs)[BK16][LDB16],
    int ar, int ac, int bkr, int bc,
    int lane, int g, int c, int m0base, int n0base)
{
    uint32_t a_s0 = sptr(&As[0][ar][ac]);
    uint32_t a_s1 = sptr(&As[1][ar][ac]);
    uint32_t b_s0 = sptr(&Bs[0][bkr][bc]);
    uint32_t b_s1 = sptr(&Bs[1][bkr][bc]);
    const float* ag = arow + ac;
    const float* bg = bcol + (size_t)bkr * ldb;

    int lrow = ((lane >> 3) & 1) * 8 + (lane & 7);
    int lcol = (lane >> 4) * 4;
    uint32_t a_lm0 = sptr(&As[0][m0base + lrow][lcol]);
    uint32_t a_lm1 = sptr(&As[1][m0base + lrow][lcol]);

    CP16(a_s0, ag); CP16(a_s0 + 16, ag + 4);
    CP16(b_s0, bg); CP16(b_s0 + 16, bg + 4);
    CPCOMMIT();

    int buf = 0;
    for (int it = 0; it < iters; it++) {
        if (it + 1 < iters) {
            const float* ag2 = ag + (it + 1) * BK16;
            const float* bg2 = bg + (size_t)(it + 1) * BK16 * ldb;
            uint32_t asn = buf ? a_s0 : a_s1;
            uint32_t bsn = buf ? b_s0 : b_s1;
            CP16(asn, ag2); CP16(asn + 16, ag2 + 4);
            CP16(bsn, bg2); CP16(bsn + 16, bg2 + 4);
            CPCOMMIT();
            CPWAIT1();
        } else {
            CPWAIT0();
        }
        __syncthreads();
        uint32_t albase = buf ? a_lm1 : a_lm0;
        #pragma unroll
        for (int kb = 0; kb < 2; kb++) {
            uint32_t bf[4][2];
            #pragma unroll
            for (int nf = 0; nf < 4; nf++) {
                int n0 = n0base + nf * 8 + g;
                bf[nf][0] = __float_as_uint(Bs[buf][kb * 8 + c][n0]);
                bf[nf][1] = __float_as_uint(Bs[buf][kb * 8 + c + 4][n0]);
            }
            #pragma unroll
            for (int mf = 0; mf < 4; mf++) {
                uint32_t fa0, fa1, fa2, fa3;
                ldsm_x4(fa0, fa1, fa2, fa3,
                        albase + (uint32_t)(mf * 16 * LDA16 * 4 + kb * 32));
                #pragma unroll
                for (int nf = 0; nf < 4; nf++)
                    mma_tf32(acc[mf * 4 + nf], fa0, fa1, fa2, fa3,
                             bf[nf][0], bf[nf][1]);
            }
        }
        __syncthreads();
        buf ^= 1;
    }
}

#define MMA_PROLOG16()                            \
    int t    = threadIdx.x;                       \
    int lane = t & 31;                            \
    int wid  = t >> 5;                            \
    int ar   = t >> 1;                            \
    int ac   = (t & 1) * 8;                       \
    int bkr  = t >> 4;                            \
    int bc   = (t & 15) * 8;                      \
    int g    = lane >> 2;                         \
    int c    = lane & 3;                          \
    int m0base = (wid & 1) * 64;                  \
    int n0base = (wid >> 1) * 32;                 \
    __shared__ float As[2][BM][LDA16];            \
    __shared__ float Bs[2][BK16][LDB16];          \
    float acc[16][4];                             \
    _Pragma("unroll")                             \
    for (int _i = 0; _i < 16; _i++)               \
        for (int _j = 0; _j < 4; _j++) acc[_i][_j] = 0.f;

// ===========================================================================
// core32: round-13 GEMM core (BK=32, 3-stage ring, ONE barrier/tile, dyn smem).
// Used by qkv_gemm / oproj_gemm (measured 110 TF/s on qkv).
// ===========================================================================
__device__ __forceinline__ void gemm_core32(
    const float* __restrict__ aptr,   // A + (bm + ar)*lda_glob + akc
    const float* __restrict__ bptr,   // B + bkr*ldb + bn + bnc
    int ldb, int iters,
    float (&acc)[16][4],
    float* __restrict__ sm,
    int lane, int m0base, int n0base,
    int ar, int akc, int bkr, int bnc)
{
    float* Ab = sm;
    float* Bb = sm + NSTAGE * A_ST;
    int g = lane >> 2, c = lane & 3;

    uint32_t aS = sptr(Ab + ar * LDA32 + akc);
    uint32_t bS = sptr(Bb + bkr * LDB32 + bnc);
    int lrow = ((lane >> 3) & 1) * 8 + (lane & 7);
    int lcol = (lane >> 4) * 4;
    uint32_t aL = sptr(Ab + (m0base + lrow) * LDA32 + lcol);
    const uint32_t ASB = A_ST * 4;
    const uint32_t BSB = B_ST * 4;

#define ISSUE32(s, it_) do {                                            \
    const float* _ag = aptr + (it_) * BK32;                             \
    uint32_t _as = aS + (uint32_t)(s) * ASB;                            \
    CP16(_as, _ag); CP16(_as + 16, _ag + 4);                            \
    CP16(_as + 32, _ag + 8); CP16(_as + 48, _ag + 12);                  \
    const float* _bg = bptr + (size_t)(it_) * BK32 * ldb;               \
    uint32_t _bs = bS + (uint32_t)(s) * BSB;                            \
    CP16(_bs, _bg); CP16(_bs + 16, _bg + 4);                            \
    CP16(_bs + 32, _bg + 8); CP16(_bs + 48, _bg + 12);                  \
    CPCOMMIT(); } while (0)

    ISSUE32(0, 0);
    ISSUE32(1, 1);

    int st = 0;
    for (int it = 0; it < iters; it++) {
        if (it + 1 < iters) CPWAIT1(); else CPWAIT0();
        __syncthreads();
        if (it + 2 < iters) {
            int sn = st + 2; if (sn >= NSTAGE) sn -= NSTAGE;
            ISSUE32(sn, it + 2);
        }
        const float* Bst = Bb + st * B_ST;
        uint32_t aLs = aL + (uint32_t)st * ASB;
        #pragma unroll
        for (int kb = 0; kb < 4; kb++) {
            uint32_t bf[4][2];
            #pragma unroll
            for (int nf = 0; nf < 4; nf++) {
                int n0 = n0base + nf * 8 + g;
                bf[nf][0] = __float_as_uint(Bst[(kb * 8 + c) * LDB32 + n0]);
                bf[nf][1] = __float_as_uint(Bst[(kb * 8 + c + 4) * LDB32 + n0]);
            }
            #pragma unroll
            for (int mf = 0; mf < 4; mf++) {
                uint32_t fa0, fa1, fa2, fa3;
                ldsm_x4(fa0, fa1, fa2, fa3,
                        aLs + (uint32_t)(mf * 16 * LDA32 * 4 + kb * 32));
                #pragma unroll
                for (int nf = 0; nf < 4; nf++)
                    mma_tf32(acc[mf * 4 + nf], fa0, fa1, fa2, fa3,
                             bf[nf][0], bf[nf][1]);
            }
        }
        if (++st == NSTAGE) st = 0;
    }
#undef ISSUE32
}

#define MMA_PROLOG32()                            \
    int t    = threadIdx.x;                       \
    int lane = t & 31;                            \
    int wid  = t >> 5;                            \
    int ar   = t >> 1;                            \
    int akc  = (t & 1) * 16;                      \
    int bkr  = t >> 3;                            \
    int bnc  = (t & 7) * 16;                      \
    int g    = lane >> 2;                         \
    int c    = lane & 3;                          \
    int m0base = (wid & 1) * 64;                  \
    int n0base = (wid >> 1) * 32;                 \
    extern __shared__ float smx[];                \
    float acc[16][4];                             \
    _Pragma("unroll")                             \
    for (int _i = 0; _i < 16; _i++)               \
        for (int _j = 0; _j < 4; _j++) acc[_i][_j] = 0.f;

// ---------------------------------------------------------------------------
// Weight tf32 pre-round (fused): small = 4 DxD weights, big = w1 + w2
// ---------------------------------------------------------------------------
__global__ void round_small(const float* __restrict__ wq, const float* __restrict__ wk,
                            const float* __restrict__ wv, const float* __restrict__ wo) {
    const float* in = (blockIdx.y == 0) ? wq : (blockIdx.y == 1) ? wk
                    : (blockIdx.y == 2) ? wv : wo;
    float* outp = (blockIdx.y == 0) ? g_wqr : (blockIdx.y == 1) ? g_wkr
                : (blockIdx.y == 2) ? g_wvr : g_wor;
    int i = blockIdx.x * 256 + threadIdx.x;
    float4 v = ((const float4*)in)[i];
    v.x = roundtf(v.x); v.y = roundtf(v.y); v.z = roundtf(v.z); v.w = roundtf(v.w);
    ((float4*)outp)[i] = v;
}

__global__ void round_big(const float* __restrict__ w1, const float* __restrict__ w2) {
    const float* in = (blockIdx.y == 0) ? w1 : w2;
    float* outp = (blockIdx.y == 0) ? g_w1r : g_w2r;
    size_t i = (size_t)blockIdx.x * 256 + threadIdx.x;
    float4 v = ((const float4*)in)[i];
    v.x = roundtf(v.x); v.y = roundtf(v.y); v.z = roundtf(v.z); v.w = roundtf(v.w);
    ((float4*)outp)[i] = v;
}

// ---------------------------------------------------------------------------
// Fused QKV projection (core32): grid (Tn/128, Dn/128, 3)
// ---------------------------------------------------------------------------
__global__ void __launch_bounds__(256, 2)
qkv_gemm(const float* __restrict__ h1) {
    const float* W = (blockIdx.z == 0) ? g_wqr : (blockIdx.z == 1) ? g_wkr : g_wvr;
    float* C = (blockIdx.z == 0) ? g_q : (blockIdx.z == 1) ? g_k : g_v;
    int bm = blockIdx.x * BM, bn = blockIdx.y * BN;
    MMA_PROLOG32();
    gemm_core32(h1 + (size_t)(bm + ar) * Dn + akc,
                W + (size_t)bkr * Dn + bn + bnc,
                Dn, Dn / BK32, acc, smx, lane, m0base, n0base, ar, akc, bkr, bnc);
    #pragma unroll
    for (int mf = 0; mf < 4; mf++) {
        int r0 = bm + m0base + mf * 16 + g;
        #pragma unroll
        for (int nf = 0; nf < 4; nf++) {
            int cb = bn + n0base + nf * 8 + c * 2;
            float* cc = acc[mf * 4 + nf];
            *(float2*)(C + (size_t)r0 * Dn + cb)       = make_float2(cc[0], cc[1]);
            *(float2*)(C + (size_t)(r0 + 8) * Dn + cb) = make_float2(cc[2], cc[3]);
        }
    }
}

// ---------------------------------------------------------------------------
// O projection + residual (core32): x1 = x + att @ wo.  grid (Tn/128, Dn/128)
// ---------------------------------------------------------------------------
__global__ void __launch_bounds__(256, 2)
oproj_gemm(const float* __restrict__ x) {
    int bm = blockIdx.x * BM, bn = blockIdx.y * BN;
    MMA_PROLOG32();
    gemm_core32(g_att + (size_t)(bm + ar) * Dn + akc,
                g_wor + (size_t)bkr * Dn + bn + bnc,
                Dn, Dn / BK32, acc, smx, lane, m0base, n0base, ar, akc, bkr, bnc);
    #pragma unroll
    for (int mf = 0; mf < 4; mf++) {
        int r0 = bm + m0base + mf * 16 + g;
        #pragma unroll
        for (int nf = 0; nf < 4; nf++) {
            int cb = bn + n0base + nf * 8 + c * 2;
            float* cc = acc[mf * 4 + nf];
            size_t p0 = (size_t)r0 * Dn + cb;
            size_t p1 = (size_t)(r0 + 8) * Dn + cb;
            float2 x0 = *(const float2*)(x + p0);
            float2 x1v = *(const float2*)(x + p1);
            *(float2*)(g_x1 + p0) = make_float2(x0.x + cc[0], x0.y + cc[1]);
            *(float2*)(g_x1 + p1) = make_float2(x1v.x + cc[2], x1v.y + cc[3]);
        }
    }
}

// ---------------------------------------------------------------------------
// MoE FFN1 (core16): gathered rows, gelu(X@w1[e] + b1[e]) -> g_mid (tf32-rounded)
// grid (Tn/128, Fn/128, E)
// ---------------------------------------------------------------------------
__global__ void __launch_bounds__(256, 2)
moe_ffn1(const float* __restrict__ b1) {
    int e = blockIdx.z;
    int cnt = g_counts[e];
    int bm = blockIdx.x * BM;
    if (bm >= cnt) return;
    int off = g_offsets[e];
    int bn = blockIdx.y * BN;
    MMA_PROLOG16();
    int arow = bm + ar; if (arow >= cnt) arow = cnt - 1;
    int tok = g_slot2tok[off + arow];
    gemm_core16(g_h2r + (size_t)tok * Dn,
                g_w1r + (size_t)e * Dn * Fn + bn + bc,
                Fn, Dn / BK16, acc, As, Bs, ar, ac, bkr, bc, lane, g, c, m0base, n0base);
    #pragma unroll
    for (int mf = 0; mf < 4; mf++) {
        int r0 = bm + m0base + mf * 16 + g;
        int r1 = r0 + 8;
        #pragma unroll
        for (int nf = 0; nf < 4; nf++) {
            int cb = bn + n0base + nf * 8 + c * 2;
            float bv0 = b1[e * Fn + cb], bv1 = b1[e * Fn + cb + 1];
            float* cc = acc[mf * 4 + nf];
            if (r0 < cnt)
                *(float2*)(g_mid + (size_t)(off + r0) * Fn + cb) =
                    make_float2(roundtf(gelu_tanh(cc[0] + bv0)),
                                roundtf(gelu_tanh(cc[1] + bv1)));
            if (r1 < cnt)
                *(float2*)(g_mid + (size_t)(off + r1) * Fn + cb) =
                    make_float2(roundtf(gelu_tanh(cc[2] + bv0)),
                                roundtf(gelu_tanh(cc[3] + bv1)));
        }
    }
}

// ---------------------------------------------------------------------------
// MoE FFN2 (core16): mid@w2[e] + b2[e] -> g_eout.  grid (Tn/128, Dn/128, E)
// ---------------------------------------------------------------------------
__global__ void __launch_bounds__(256, 2)
moe_ffn2(const float* __restrict__ b2) {
    int e = blockIdx.z;
    int cnt = g_counts[e];
    int bm = blockIdx.x * BM;
    if (bm >= cnt) return;
    int off = g_offsets[e];
    int bn = blockIdx.y * BN;
    MMA_PROLOG16();
    int arow = bm + ar; if (arow >= cnt) arow = cnt - 1;
    gemm_core16(g_mid + (size_t)(off + arow) * Fn,
                g_w2r + (size_t)e * Fn * Dn + bn + bc,
                Dn, Fn / BK16, acc, As, Bs, ar, ac, bkr, bc, lane, g, c, m0base, n0base);
    #pragma unroll
    for (int mf = 0; mf < 4; mf++) {
        int r0 = bm + m0base + mf * 16 + g;
        int r1 = r0 + 8;
        #pragma unroll
        for (int nf = 0; nf < 4; nf++) {
            int cb = bn + n0base + nf * 8 + c * 2;
            float bv0 = b2[e * Dn + cb], bv1 = b2[e * Dn + cb + 1];
            float* cc = acc[mf * 4 + nf];
            if (r0 < cnt)
                *(float2*)(g_eout + (size_t)(off + r0) * Dn + cb) =
                    make_float2(cc[0] + bv0, cc[1] + bv1);
            if (r1 < cnt)
                *(float2*)(g_eout + (size_t)(off + r1) * Dn + cb) =
                    make_float2(cc[2] + bv0, cc[3] + bv1);
        }
    }
}

// ---------------------------------------------------------------------------
// LayerNorm: one block per token, 256 threads, D=768 (3 elems/thread).
// out = tf32-rounded LN (feeds GEMM A); out2 (optional) = exact LN (routing).
// ---------------------------------------------------------------------------
__global__ void ln_kernel(const float* __restrict__ x,
                          const float* __restrict__ g,
                          const float* __restrict__ b,
                          float* __restrict__ out,
                          float* __restrict__ out2) {
    int t = blockIdx.x;
    const float* row = x + (size_t)t * Dn;
    int tid = threadIdx.x;
    float v0 = row[tid], v1 = row[tid + 256], v2 = row[tid + 512];
    float s  = v0 + v1 + v2;
    float ss = v0 * v0 + v1 * v1 + v2 * v2;
    #pragma unroll
    for (int o = 16; o; o >>= 1) {
        s  += __shfl_down_sync(0xffffffffu, s, o);
        ss += __shfl_down_sync(0xffffffffu, ss, o);
    }
    __shared__ float rs[8], rss[8];
    __shared__ float mu_s, rstd_s;
    int w = tid >> 5, l = tid & 31;
    if (l == 0) { rs[w] = s; rss[w] = ss; }
    __syncthreads();
    if (tid == 0) {
        float S = 0.f, SS = 0.f;
        #pragma unroll
        for (int i = 0; i < 8; i++) { S += rs[i]; SS += rss[i]; }
        float mu  = S / (float)Dn;
        float var = SS / (float)Dn - mu * mu;
        mu_s = mu; rstd_s = rsqrtf(var + 1e-5f);
    }
    __syncthreads();
    float mu = mu_s, rstd = rstd_s;
    float* orow = out + (size_t)t * Dn;
    float e0 = (v0 - mu) * rstd * g[tid]       + b[tid];
    float e1 = (v1 - mu) * rstd * g[tid + 256] + b[tid + 256];
    float e2 = (v2 - mu) * rstd * g[tid + 512] + b[tid + 512];
    orow[tid]       = roundtf(e0);
    orow[tid + 256] = roundtf(e1);
    orow[tid + 512] = roundtf(e2);
    if (out2) {
        float* xrow = out2 + (size_t)t * Dn;
        xrow[tid] = e0; xrow[tid + 256] = e1; xrow[tid + 512] = e2;
    }
}

// ---------------------------------------------------------------------------
// Flash-style attention: grid (S/128, H, B), 128 threads; one thread = one q row.
// Output tf32-rounded (feeds oproj A).
// ---------------------------------------------------------------------------
__global__ void __launch_bounds__(128)
attn_kernel(const float* __restrict__ q, const float* __restrict__ k,
            const float* __restrict__ v, float* __restrict__ o_out) {
    const int KT = 32;
    int h = blockIdx.y, b = blockIdx.z;
    int tid = threadIdx.x;
    int qrow = b * Sn + blockIdx.x * 128 + tid;
    const float* qptr = q + (size_t)qrow * Dn + h * DHn;
    float qreg[64];
    #pragma unroll
    for (int d = 0; d < 64; d++) qreg[d] = qptr[d] * 0.125f;  // 1/sqrt(64)
    float oacc[64];
    #pragma unroll
    for (int d = 0; d < 64; d++) oacc[d] = 0.f;
    float m = -1e30f, lsum = 0.f;

    __shared__ float Ks[KT][64], Vs[KT][64];
    for (int k0 = 0; k0 < Sn; k0 += KT) {
        for (int i = tid; i < KT * 64; i += 128) {
            int r = i >> 6, ccol = i & 63;
            size_t src = (size_t)(b * Sn + k0 + r) * Dn + h * DHn + ccol;
            Ks[r][ccol] = k[src];
            Vs[r][ccol] = v[src];
        }
        __syncthreads();
        float sv[KT];
        float smax = -1e30f;
        #pragma unroll
        for (int j = 0; j < KT; j++) {
            float s = 0.f;
            #pragma unroll
            for (int d = 0; d < 64; d++) s += qreg[d] * Ks[j][d];
            sv[j] = s;
            smax = fmaxf(smax, s);
        }
        float mnew = fmaxf(m, smax);
        float alpha = expf(m - mnew);
        float psum = 0.f;
        #pragma unroll
        for (int j = 0; j < KT; j++) { float p = expf(sv[j] - mnew); sv[j] = p; psum += p; }
        lsum = lsum * alpha + psum;
        #pragma unroll
        for (int d = 0; d < 64; d++) {
            float a = 0.f;
            #pragma unroll
            for (int j = 0; j < KT; j++) a += sv[j] * Vs[j][d];
            oacc[d] = oacc[d] * alpha + a;
        }
        m = mnew;
        __syncthreads();
    }
    float inv = 1.0f / lsum;
    float* op = o_out + (size_t)qrow * Dn + h * DHn;
    #pragma unroll
    for (int d = 0; d < 64; d++) op[d] = roundtf(oacc[d] * inv);
}

// ---------------------------------------------------------------------------
// MoE routing (reads EXACT h2 + exact gate_w: selection identical to reference)
// ---------------------------------------------------------------------------
__global__ void zero_counts_kernel() {
    if (threadIdx.x < En) g_counts[threadIdx.x] = 0;
}

__global__ void routing_kernel(const float* __restrict__ h2,
                               const float* __restrict__ gate_w,
                               const float* __restrict__ gate_b,
                               const float* __restrict__ bias_e) {
    int t = blockIdx.x;
    int wid = threadIdx.x >> 5, lane = threadIdx.x & 31;
    __shared__ float logit[En];
    float s = 0.f;
    const float* row = h2 + (size_t)t * Dn;
    for (int d = lane; d < Dn; d += 32) s += row[d] * gate_w[d * En + wid];
    #pragma unroll
    for (int o = 16; o; o >>= 1) s += __shfl_down_sync(0xffffffffu, s, o);
    if (lane == 0) logit[wid] = s + gate_b[wid];   // TAU = 1
    __syncthreads();
    if (threadIdx.x == 0) {
        float sel[En];
        #pragma unroll
        for (int e = 0; e < En; e++) sel[e] = logit[e] + bias_e[e];
        int i0 = 0;
        #pragma unroll
        for (int e = 1; e < En; e++) if (sel[e] > sel[i0]) i0 = e;
        int i1 = (i0 == 0) ? 1 : 0;
        #pragma unroll
        for (int e = 0; e < En; e++) if (e != i0 && sel[e] > sel[i1]) i1 = e;
        float l0 = logit[i0], l1 = logit[i1];
        float mm = fmaxf(l0, l1);
        float e0 = expf(l0 - mm), e1 = expf(l1 - mm);
        float inv = 1.0f / (e0 + e1);
        g_idx[t * 2] = i0;     g_idx[t * 2 + 1] = i1;
        g_gate[t * 2] = e0 * inv; g_gate[t * 2 + 1] = e1 * inv;
        g_pos[t * 2]     = atomicAdd(&g_counts[i0], 1);
        g_pos[t * 2 + 1] = atomicAdd(&g_counts[i1], 1);
    }
}

__global__ void offsets_kernel() {
    if (threadIdx.x == 0) {
        int acc = 0;
        for (int e = 0; e < En; e++) { g_offsets[e] = acc; acc += g_counts[e]; }
    }
}

__global__ void fill_slots_kernel() {
    int t = blockIdx.x * 256 + threadIdx.x;
    if (t >= Tn) return;
    #pragma unroll
    for (int kk = 0; kk < 2; kk++) {
        int e = g_idx[t * 2 + kk];
        int slot = g_offsets[e] + g_pos[t * 2 + kk];
        g_slotof[t * 2 + kk] = slot;
        g_slot2tok[slot] = t;
    }
}

// ---------------------------------------------------------------------------
// Final combine: out = x1 + g0*eout[slot0] + g1*eout[slot1]
// ---------------------------------------------------------------------------
__global__ void combine_kernel(const float* __restrict__ x1, float* __restrict__ out) {
    int t = blockIdx.x;
    int d = blockIdx.y * 256 + threadIdx.x;
    int s0 = g_slotof[t * 2], s1 = g_slotof[t * 2 + 1];
    float g0 = g_gate[t * 2], g1 = g_gate[t * 2 + 1];
    out[(size_t)t * Dn + d] = x1[(size_t)t * Dn + d]
                            + g0 * g_eout[(size_t)s0 * Dn + d]
                            + g1 * g_eout[(size_t)s1 * Dn + d];
}

// ---------------------------------------------------------------------------
// launch
// ---------------------------------------------------------------------------
extern "C" void kernel_launch(void* const* d_in, const int* in_sizes, int n_in,
                              void* d_out, int out_size) {
    const float* x      = (const float*)d_in[0];
    const float* wq     = (const float*)d_in[1];
    const float* wk     = (const float*)d_in[2];
    const float* wv     = (const float*)d_in[3];
    const float* wo     = (const float*)d_in[4];
    const float* ln1_g  = (const float*)d_in[5];
    const float* ln1_b  = (const float*)d_in[6];
    const float* ln2_g  = (const float*)d_in[7];
    const float* ln2_b  = (const float*)d_in[8];
    const float* gate_w = (const float*)d_in[9];
    const float* gate_b = (const float*)d_in[10];
    const float* bias_e = (const float*)d_in[11];
    const float* w1     = (const float*)d_in[12];
    const float* b1     = (const float*)d_in[13];
    const float* w2     = (const float*)d_in[14];
    const float* b2     = (const float*)d_in[15];
    float* out = (float*)d_out;

    float *h1, *qb, *kb, *vb, *att, *x1, *h2r, *h2x;
    cudaGetSymbolAddress((void**)&h1,  g_h1);
    cudaGetSymbolAddress((void**)&qb,  g_q);
    cudaGetSymbolAddress((void**)&kb,  g_k);
    cudaGetSymbolAddress((void**)&vb,  g_v);
    cudaGetSymbolAddress((void**)&att, g_att);
    cudaGetSymbolAddress((void**)&x1,  g_x1);
    cudaGetSymbolAddress((void**)&h2r, g_h2r);
    cudaGetSymbolAddress((void**)&h2x, g_h2x);

    // raise dynamic smem limits for the core32 kernels (host-side attribute)
    static int smem_set = 0;
    if (!smem_set) {
        cudaFuncSetAttribute(qkv_gemm,   cudaFuncAttributeMaxDynamicSharedMemorySize, SMEM_SZ);
        cudaFuncSetAttribute(oproj_gemm, cudaFuncAttributeMaxDynamicSharedMemorySize, SMEM_SZ);
        smem_set = 1;
    }

    // --- tf32 pre-round of weights (2 fused launches) ---
    const int DD4 = Dn * Dn / 4;                  // 147456
    const int W4  = En * Dn * Fn / 4;             // 4718592
    round_small<<<dim3(DD4 / 256, 4), 256>>>(wq, wk, wv, wo);
    round_big<<<dim3(W4 / 256, 2), 256>>>(w1, w2);

    // --- attention block ---
    ln_kernel<<<Tn, 256>>>(x, ln1_g, ln1_b, h1, nullptr);
    qkv_gemm<<<dim3(Tn / BM, Dn / BN, 3), 256, SMEM_SZ>>>(h1);
    attn_kernel<<<dim3(Sn / 128, Hn, Bsz), 128>>>(qb, kb, vb, att);
    oproj_gemm<<<dim3(Tn / BM, Dn / BN), 256, SMEM_SZ>>>(x);

    // --- MoE block ---
    ln_kernel<<<Tn, 256>>>(x1, ln2_g, ln2_b, h2r, h2x);
    zero_counts_kernel<<<1, 32>>>();
    routing_kernel<<<Tn, 256>>>(h2x, gate_w, gate_b, bias_e);
    offsets_kernel<<<1, 32>>>();
    fill_slots_kernel<<<Tn / 256, 256>>>();
    moe_ffn1<<<dim3(Tn / BM, Fn / BN, En), 256>>>(b1);
    moe_ffn2<<<dim3(Tn / BM, Dn / BN, En), 256>>>(b2);
    combine_kernel<<<dim3(Tn, Dn / 256), 256>>>(x1, out);
}

// round 17
// speedup vs baseline: 1.2838x; 1.2046x over previous
#include <cuda_runtime.h>
#include <cuda_fp16.h>
#include <math.h>
#include <stdint.h>

// ---- problem dims ----
#define Tn 4096      // B*S tokens
#define Dn 768
#define Hn 12
#define DHn 64
#define Sn 512
#define Bsz 8
#define En 8
#define Fn 3072
#define TOPK 2

#define BM 128
#define BN 128

// ---- core32 (dense proj, tf32): BK=32, 3-stage ring, dynamic smem ----
#define BK32 32
#define LDA32 36
#define LDB32 136
#define A_ST (BM * LDA32)           // 4608 words/stage
#define B_ST (BK32 * LDB32)         // 4352 words/stage
#define NSTAGE 3
#define SMEM_SZ (NSTAGE * (A_ST + B_ST) * 4)   // 107,520 bytes

// ---- fp16 FFN core: BK=64 halves, 2-stage, row-major smem + ldmatrix ----
#define BKF 64
#define FROWB 144                   // bytes per smem row: 64 fp16 (128B) + 16B pad
#define FTILE (128 * FROWB)         // 18432 B per operand per stage
#define FF_SMEM (4 * FTILE)         // 73,728 bytes (A0 A1 B0 B1)

// ---- scratch (device globals: allocation-free per harness rules) ----
__device__ float g_h1[Tn * Dn];
__device__ float g_q[Tn * Dn];
__device__ float g_k[Tn * Dn];
__device__ float g_v[Tn * Dn];
__device__ float g_att[Tn * Dn];
__device__ float g_x1[Tn * Dn];
__device__ float g_h2x[Tn * Dn];                        // exact LN2 (routing)
__device__ __half g_h2h[Tn * Dn];                       // fp16 LN2 (FFN1 A)
__device__ __half g_midh[(size_t)Tn * TOPK * Fn];       // fp16 gelu out (~50 MB)
__device__ float g_eout[Tn * TOPK * Dn];                // fp32 expert out (~25 MB)
// tf32-rounded dense-proj weights; fp16 transposed FFN weights
__device__ float g_wqr[Dn * Dn];
__device__ float g_wkr[Dn * Dn];
__device__ float g_wvr[Dn * Dn];
__device__ float g_wor[Dn * Dn];
__device__ __half g_w1h[(size_t)En * Fn * Dn];          // w1^T [E][F][D] fp16
__device__ __half g_w2h[(size_t)En * Dn * Fn];          // w2^T [E][D][F] fp16
__device__ int   g_idx[Tn * TOPK];
__device__ float g_gate[Tn * TOPK];
__device__ int   g_pos[Tn * TOPK];
__device__ int   g_slotof[Tn * TOPK];
__device__ int   g_slot2tok[Tn * TOPK];
__device__ int   g_counts[En];
__device__ int   g_offsets[En];

// ---- helpers ----
__device__ __forceinline__ float gelu_tanh(float x) {
    const float c = 0.7978845608028654f;   // sqrt(2/pi)
    float t = tanhf(c * (x + 0.044715f * x * x * x));
    return 0.5f * x * (1.0f + t);
}

__device__ __forceinline__ uint32_t f2tf(float x) {
    uint32_t r;
    asm("cvt.rna.tf32.f32 %0, %1;" : "=r"(r) : "f"(x));
    return r;
}
__device__ __forceinline__ float roundtf(float x) { return __uint_as_float(f2tf(x)); }

__device__ __forceinline__ void mma_tf32(float* cc,
    uint32_t a0, uint32_t a1, uint32_t a2, uint32_t a3,
    uint32_t b0, uint32_t b1) {
    asm volatile(
        "mma.sync.aligned.m16n8k8.row.col.f32.tf32.tf32.f32 "
        "{%0,%1,%2,%3},{%4,%5,%6,%7},{%8,%9},{%0,%1,%2,%3};"
        : "+f"(cc[0]), "+f"(cc[1]), "+f"(cc[2]), "+f"(cc[3])
        : "r"(a0), "r"(a1), "r"(a2), "r"(a3), "r"(b0), "r"(b1));
}

__device__ __forceinline__ void mma_f16(float* cc,
    uint32_t a0, uint32_t a1, uint32_t a2, uint32_t a3,
    uint32_t b0, uint32_t b1) {
    asm volatile(
        "mma.sync.aligned.m16n8k16.row.col.f32.f16.f16.f32 "
        "{%0,%1,%2,%3},{%4,%5,%6,%7},{%8,%9},{%0,%1,%2,%3};"
        : "+f"(cc[0]), "+f"(cc[1]), "+f"(cc[2]), "+f"(cc[3])
        : "r"(a0), "r"(a1), "r"(a2), "r"(a3), "r"(b0), "r"(b1));
}

__device__ __forceinline__ void ldsm_x4(uint32_t& r0, uint32_t& r1,
                                        uint32_t& r2, uint32_t& r3, uint32_t addr) {
    asm volatile("ldmatrix.sync.aligned.m8n8.x4.shared.b16 {%0,%1,%2,%3}, [%4];"
                 : "=r"(r0), "=r"(r1), "=r"(r2), "=r"(r3) : "r"(addr));
}

__device__ __forceinline__ uint32_t sptr(const void* p) {
    return (uint32_t)__cvta_generic_to_shared(p);
}
#define CP16(s, g) asm volatile("cp.async.cg.shared.global [%0], [%1], 16;" :: "r"(s), "l"(g))
#define CPCOMMIT() asm volatile("cp.async.commit_group;")
#define CPWAIT1()  asm volatile("cp.async.wait_group 1;")
#define CPWAIT0()  asm volatile("cp.async.wait_group 0;")

// ===========================================================================
// core32: tf32 mma.sync GEMM core for dense projections (measured 110 TF/s).
// ===========================================================================
__device__ __forceinline__ void gemm_core32(
    const float* __restrict__ aptr, const float* __restrict__ bptr,
    int ldb, int iters, float (&acc)[16][4], float* __restrict__ sm,
    int lane, int m0base, int n0base, int ar, int akc, int bkr, int bnc)
{
    float* Ab = sm;
    float* Bb = sm + NSTAGE * A_ST;
    int g = lane >> 2, c = lane & 3;

    uint32_t aS = sptr(Ab + ar * LDA32 + akc);
    uint32_t bS = sptr(Bb + bkr * LDB32 + bnc);
    int lrow = ((lane >> 3) & 1) * 8 + (lane & 7);
    int lcol = (lane >> 4) * 4;
    uint32_t aL = sptr(Ab + (m0base + lrow) * LDA32 + lcol);
    const uint32_t ASB = A_ST * 4;
    const uint32_t BSB = B_ST * 4;

#define ISSUE32(s, it_) do {                                            \
    const float* _ag = aptr + (it_) * BK32;                             \
    uint32_t _as = aS + (uint32_t)(s) * ASB;                            \
    CP16(_as, _ag); CP16(_as + 16, _ag + 4);                            \
    CP16(_as + 32, _ag + 8); CP16(_as + 48, _ag + 12);                  \
    const float* _bg = bptr + (size_t)(it_) * BK32 * ldb;               \
    uint32_t _bs = bS + (uint32_t)(s) * BSB;                            \
    CP16(_bs, _bg); CP16(_bs + 16, _bg + 4);                            \
    CP16(_bs + 32, _bg + 8); CP16(_bs + 48, _bg + 12);                  \
    CPCOMMIT(); } while (0)

    ISSUE32(0, 0);
    ISSUE32(1, 1);

    int st = 0;
    for (int it = 0; it < iters; it++) {
        if (it + 1 < iters) CPWAIT1(); else CPWAIT0();
        __syncthreads();
        if (it + 2 < iters) {
            int sn = st + 2; if (sn >= NSTAGE) sn -= NSTAGE;
            ISSUE32(sn, it + 2);
        }
        const float* Bst = Bb + st * B_ST;
        uint32_t aLs = aL + (uint32_t)st * ASB;
        #pragma unroll
        for (int kb = 0; kb < 4; kb++) {
            uint32_t bf[4][2];
            #pragma unroll
            for (int nf = 0; nf < 4; nf++) {
                int n0 = n0base + nf * 8 + g;
                bf[nf][0] = __float_as_uint(Bst[(kb * 8 + c) * LDB32 + n0]);
                bf[nf][1] = __float_as_uint(Bst[(kb * 8 + c + 4) * LDB32 + n0]);
            }
            #pragma unroll
            for (int mf = 0; mf < 4; mf++) {
                uint32_t fa0, fa1, fa2, fa3;
                ldsm_x4(fa0, fa1, fa2, fa3,
                        aLs + (uint32_t)(mf * 16 * LDA32 * 4 + kb * 32));
                #pragma unroll
                for (int nf = 0; nf < 4; nf++)
                    mma_tf32(acc[mf * 4 + nf], fa0, fa1, fa2, fa3,
                             bf[nf][0], bf[nf][1]);
            }
        }
        if (++st == NSTAGE) st = 0;
    }
#undef ISSUE32
}

#define MMA_PROLOG32()                            \
    int t    = threadIdx.x;                       \
    int lane = t & 31;                            \
    int wid  = t >> 5;                            \
    int ar   = t >> 1;                            \
    int akc  = (t & 1) * 16;                      \
    int bkr  = t >> 3;                            \
    int bnc  = (t & 7) * 16;                      \
    int g    = lane >> 2;                         \
    int c    = lane & 3;                          \
    int m0base = (wid & 1) * 64;                  \
    int n0base = (wid >> 1) * 32;                 \
    extern __shared__ float smx[];                \
    float acc[16][4];                             \
    _Pragma("unroll")                             \
    for (int _i = 0; _i < 16; _i++)               \
        for (int _j = 0; _j < 4; _j++) acc[_i][_j] = 0.f;

// ---------------------------------------------------------------------------
// Weight prep
// ---------------------------------------------------------------------------
__global__ void round_small(const float* __restrict__ wq, const float* __restrict__ wk,
                            const float* __restrict__ wv, const float* __restrict__ wo) {
    const float* in = (blockIdx.y == 0) ? wq : (blockIdx.y == 1) ? wk
                    : (blockIdx.y == 2) ? wv : wo;
    float* outp = (blockIdx.y == 0) ? g_wqr : (blockIdx.y == 1) ? g_wkr
                : (blockIdx.y == 2) ? g_wvr : g_wor;
    int i = blockIdx.x * 256 + threadIdx.x;
    float4 v = ((const float4*)in)[i];
    v.x = roundtf(v.x); v.y = roundtf(v.y); v.z = roundtf(v.z); v.w = roundtf(v.w);
    ((float4*)outp)[i] = v;
}

// [R,C] fp32 -> out [C,R] fp16, per expert. block (32,8), grid (C/32, R/32, E)
__global__ void transpose_h(const float* __restrict__ in, __half* __restrict__ outp,
                            int R, int C) {
    __shared__ float ts[32][33];
    int e = blockIdx.z;
    const float* I = in + (size_t)e * R * C;
    __half* O = outp + (size_t)e * R * C;
    int c0 = blockIdx.x * 32, r0 = blockIdx.y * 32;
    int tx = threadIdx.x, ty = threadIdx.y;
    #pragma unroll
    for (int i = 0; i < 4; i++) {
        int r = r0 + ty + i * 8;
        ts[ty + i * 8][tx] = I[(size_t)r * C + c0 + tx];
    }
    __syncthreads();
    #pragma unroll
    for (int i = 0; i < 4; i++) {
        int cc = c0 + ty + i * 8;
        O[(size_t)cc * R + r0 + tx] = __float2half_rn(ts[tx][ty + i * 8]);
    }
}

// ---------------------------------------------------------------------------
// Fused QKV projection (core32): grid (Tn/128, Dn/128, 3)
// ---------------------------------------------------------------------------
__global__ void __launch_bounds__(256, 2)
qkv_gemm(const float* __restrict__ h1) {
    const float* W = (blockIdx.z == 0) ? g_wqr : (blockIdx.z == 1) ? g_wkr : g_wvr;
    float* C = (blockIdx.z == 0) ? g_q : (blockIdx.z == 1) ? g_k : g_v;
    int bm = blockIdx.x * BM, bn = blockIdx.y * BN;
    MMA_PROLOG32();
    gemm_core32(h1 + (size_t)(bm + ar) * Dn + akc,
                W + (size_t)bkr * Dn + bn + bnc,
                Dn, Dn / BK32, acc, smx, lane, m0base, n0base, ar, akc, bkr, bnc);
    #pragma unroll
    for (int mf = 0; mf < 4; mf++) {
        int r0 = bm + m0base + mf * 16 + g;
        #pragma unroll
        for (int nf = 0; nf < 4; nf++) {
            int cb = bn + n0base + nf * 8 + c * 2;
            float* cc = acc[mf * 4 + nf];
            *(float2*)(C + (size_t)r0 * Dn + cb)       = make_float2(cc[0], cc[1]);
            *(float2*)(C + (size_t)(r0 + 8) * Dn + cb) = make_float2(cc[2], cc[3]);
        }
    }
}

// ---------------------------------------------------------------------------
// O projection + residual (core32): x1 = x + att @ wo.  grid (Tn/128, Dn/128)
// ---------------------------------------------------------------------------
__global__ void __launch_bounds__(256, 2)
oproj_gemm(const float* __restrict__ x) {
    int bm = blockIdx.x * BM, bn = blockIdx.y * BN;
    MMA_PROLOG32();
    gemm_core32(g_att + (size_t)(bm + ar) * Dn + akc,
                g_wor + (size_t)bkr * Dn + bn + bnc,
                Dn, Dn / BK32, acc, smx, lane, m0base, n0base, ar, akc, bkr, bnc);
    #pragma unroll
    for (int mf = 0; mf < 4; mf++) {
        int r0 = bm + m0base + mf * 16 + g;
        #pragma unroll
        for (int nf = 0; nf < 4; nf++) {
            int cb = bn + n0base + nf * 8 + c * 2;
            float* cc = acc[mf * 4 + nf];
            size_t p0 = (size_t)r0 * Dn + cb;
            size_t p1 = (size_t)(r0 + 8) * Dn + cb;
            float2 x0 = *(const float2*)(x + p0);
            float2 x1v = *(const float2*)(x + p1);
            *(float2*)(g_x1 + p0) = make_float2(x0.x + cc[0], x0.y + cc[1]);
            *(float2*)(g_x1 + p1) = make_float2(x1v.x + cc[2], x1v.y + cc[3]);
        }
    }
}

// ---------------------------------------------------------------------------
// fp16 MoE FFN (m16n8k16): C = act(A @ Wt[e]^T + bias[e])
// A: [rows][Ktot] fp16 K-major. Wt: [E][Ntot][Ktot] fp16 K-major.
// grid (Tn/128, Ntot/128, E), 256 threads, dyn smem FF_SMEM.
// Smem layout per stage: [128 rows][FROWB bytes] (64 fp16 + pad).
// ldmatrix.x4 (no trans) for BOTH operands (fragment maps verified):
//   A (mf): tiles (m0-7,k0-7)(m8-15,k0-7)(m0-7,k8-15)(m8-15,k8-15) -> a0..a3
//   B x4 over rows n0..n0+15 gives {b0,b1} for two nf at once.
// ---------------------------------------------------------------------------
__global__ void __launch_bounds__(256, 2)
moe_ffn_h(const __half* __restrict__ Abase,
          const __half* __restrict__ Wt,
          const float* __restrict__ bias,
          __half* __restrict__ OutH,   // fp16+gelu out (FFN1) or null
          float* __restrict__ OutF,    // fp32 out (FFN2) or null
          int Ktot, int Ntot, int gather)
{
    int e = blockIdx.z;
    int cnt = g_counts[e];
    int bm = blockIdx.x * BM;
    if (bm >= cnt) return;
    int off = g_offsets[e];
    int bn = blockIdx.y * BN;
    int t = threadIdx.x, lane = t & 31, wid = t >> 5;
    int g = lane >> 2, c = lane & 3;
    int m0base = (wid & 1) * 64;
    int n0base = (wid >> 1) * 32;
    extern __shared__ char fs[];

    // staging: thread t covers row r, 4 consecutive 16B chunks starting j0
    int r = t >> 1, j0 = (t & 1) * 4;
    int arow = bm + r; if (arow >= cnt) arow = cnt - 1;
    int tok = gather ? g_slot2tok[off + arow] : (off + arow);
    const __half* ag = Abase + (size_t)tok * Ktot + j0 * 8;
    const __half* bg = Wt + ((size_t)e * Ntot + bn + r) * Ktot + j0 * 8;
    uint32_t swA = sptr(fs) + (uint32_t)(r * FROWB + j0 * 16);
    uint32_t swB = swA + 2u * FTILE;

    // ldmatrix lane addressing (buffer 0 bases)
    int lrow = ((lane >> 3) & 1) * 8 + (lane & 7);
    int kgrp = lane >> 4;   // 0: k0-7, 1: k8-15 (16B apart)
    uint32_t aLm = sptr(fs) + (uint32_t)((m0base + lrow) * FROWB + kgrp * 16);
    uint32_t bLm = sptr(fs) + 2u * FTILE + (uint32_t)((n0base + lrow) * FROWB + kgrp * 16);

    float acc[16][4];
    #pragma unroll
    for (int i = 0; i < 16; i++)
        #pragma unroll
        for (int j = 0; j < 4; j++) acc[i][j] = 0.f;

#define FISSUE(buf, it_) do {                                           \
    uint32_t _a = swA + (uint32_t)(buf) * FTILE;                        \
    uint32_t _b = swB + (uint32_t)(buf) * FTILE;                        \
    const __half* _ag = ag + (size_t)(it_) * BKF;                       \
    const __half* _bg = bg + (size_t)(it_) * BKF;                       \
    CP16(_a, _ag); CP16(_a + 16, _ag + 8);                              \
    CP16(_a + 32, _ag + 16); CP16(_a + 48, _ag + 24);                   \
    CP16(_b, _bg); CP16(_b + 16, _bg + 8);                              \
    CP16(_b + 32, _bg + 16); CP16(_b + 48, _bg + 24);                   \
    CPCOMMIT(); } while (0)

    int iters = Ktot / BKF;
    FISSUE(0, 0);
    FISSUE(1, 1);

    int buf = 0;
    for (int it = 0; it < iters; it++) {
        if (it + 1 < iters) CPWAIT1(); else CPWAIT0();
        __syncthreads();
        uint32_t aB = aLm + (uint32_t)buf * FTILE;
        uint32_t bB = bLm + (uint32_t)buf * FTILE;
        #pragma unroll
        for (int kb = 0; kb < 4; kb++) {            // 4 x k16 per 64-K tile
            uint32_t bfr[2][4];
            ldsm_x4(bfr[0][0], bfr[0][1], bfr[0][2], bfr[0][3],
                    bB + (uint32_t)(kb * 32));
            ldsm_x4(bfr[1][0], bfr[1][1], bfr[1][2], bfr[1][3],
                    bB + (uint32_t)(16 * FROWB + kb * 32));
            #pragma unroll
            for (int mf = 0; mf < 4; mf++) {
                uint32_t a0, a1, a2, a3;
                ldsm_x4(a0, a1, a2, a3, aB + (uint32_t)(mf * 16 * FROWB + kb * 32));
                #pragma unroll
                for (int nf = 0; nf < 4; nf++) {
                    int p = nf >> 1, q = nf & 1;
                    mma_f16(acc[mf * 4 + nf], a0, a1, a2, a3,
                            bfr[p][q], bfr[p][q + 2]);
                }
            }
        }
        __syncthreads();
        if (it + 2 < iters) FISSUE(buf, it + 2);
        buf ^= 1;
    }
#undef FISSUE

    #pragma unroll
    for (int mf = 0; mf < 4; mf++) {
        int r0 = bm + m0base + mf * 16 + g;
        int r1 = r0 + 8;
        #pragma unroll
        for (int nf = 0; nf < 4; nf++) {
            int cb = bn + n0base + nf * 8 + c * 2;
            float bv0 = bias[(size_t)e * Ntot + cb];
            float bv1 = bias[(size_t)e * Ntot + cb + 1];
            float* cc = acc[mf * 4 + nf];
            if (OutH) {
                if (r0 < cnt)
                    *(__half2*)(OutH + (size_t)(off + r0) * Ntot + cb) =
                        __floats2half2_rn(gelu_tanh(cc[0] + bv0),
                                          gelu_tanh(cc[1] + bv1));
                if (r1 < cnt)
                    *(__half2*)(OutH + (size_t)(off + r1) * Ntot + cb) =
                        __floats2half2_rn(gelu_tanh(cc[2] + bv0),
                                          gelu_tanh(cc[3] + bv1));
            } else {
                if (r0 < cnt)
                    *(float2*)(OutF + (size_t)(off + r0) * Ntot + cb) =
                        make_float2(cc[0] + bv0, cc[1] + bv1);
                if (r1 < cnt)
                    *(float2*)(OutF + (size_t)(off + r1) * Ntot + cb) =
                        make_float2(cc[2] + bv0, cc[3] + bv1);
            }
        }
    }
}

// ---------------------------------------------------------------------------
// LayerNorm: one block per token, 256 threads, D=768 (3 elems/thread).
// Writes any subset of: tf32-rounded (dense A), exact (routing), fp16 (FFN A).
// ---------------------------------------------------------------------------
__global__ void ln_kernel(const float* __restrict__ x,
                          const float* __restrict__ g,
                          const float* __restrict__ b,
                          float* __restrict__ out_tf,
                          float* __restrict__ out_ex,
                          __half* __restrict__ out_h) {
    int t = blockIdx.x;
    const float* row = x + (size_t)t * Dn;
    int tid = threadIdx.x;
    float v0 = row[tid], v1 = row[tid + 256], v2 = row[tid + 512];
    float s  = v0 + v1 + v2;
    float ss = v0 * v0 + v1 * v1 + v2 * v2;
    #pragma unroll
    for (int o = 16; o; o >>= 1) {
        s  += __shfl_down_sync(0xffffffffu, s, o);
        ss += __shfl_down_sync(0xffffffffu, ss, o);
    }
    __shared__ float rs[8], rss[8];
    __shared__ float mu_s, rstd_s;
    int w = tid >> 5, l = tid & 31;
    if (l == 0) { rs[w] = s; rss[w] = ss; }
    __syncthreads();
    if (tid == 0) {
        float S = 0.f, SS = 0.f;
        #pragma unroll
        for (int i = 0; i < 8; i++) { S += rs[i]; SS += rss[i]; }
        float mu  = S / (float)Dn;
        float var = SS / (float)Dn - mu * mu;
        mu_s = mu; rstd_s = rsqrtf(var + 1e-5f);
    }
    __syncthreads();
    float mu = mu_s, rstd = rstd_s;
    float e0 = (v0 - mu) * rstd * g[tid]       + b[tid];
    float e1 = (v1 - mu) * rstd * g[tid + 256] + b[tid + 256];
    float e2 = (v2 - mu) * rstd * g[tid + 512] + b[tid + 512];
    if (out_tf) {
        float* orow = out_tf + (size_t)t * Dn;
        orow[tid] = roundtf(e0); orow[tid + 256] = roundtf(e1); orow[tid + 512] = roundtf(e2);
    }
    if (out_ex) {
        float* xrow = out_ex + (size_t)t * Dn;
        xrow[tid] = e0; xrow[tid + 256] = e1; xrow[tid + 512] = e2;
    }
    if (out_h) {
        __half* hrow = out_h + (size_t)t * Dn;
        hrow[tid]       = __float2half_rn(e0);
        hrow[tid + 256] = __float2half_rn(e1);
        hrow[tid + 512] = __float2half_rn(e2);
    }
}

// ---------------------------------------------------------------------------
// Flash-style attention: grid (S/128, H, B), 128 threads; one thread = one q row.
// ---------------------------------------------------------------------------
__global__ void __launch_bounds__(128)
attn_kernel(const float* __restrict__ q, const float* __restrict__ k,
            const float* __restrict__ v, float* __restrict__ o_out) {
    const int KT = 32;
    int h = blockIdx.y, b = blockIdx.z;
    int tid = threadIdx.x;
    int qrow = b * Sn + blockIdx.x * 128 + tid;
    const float* qptr = q + (size_t)qrow * Dn + h * DHn;
    float qreg[64];
    #pragma unroll
    for (int d = 0; d < 64; d++) qreg[d] = qptr[d] * 0.125f;  // 1/sqrt(64)
    float oacc[64];
    #pragma unroll
    for (int d = 0; d < 64; d++) oacc[d] = 0.f;
    float m = -1e30f, lsum = 0.f;

    __shared__ float Ks[KT][64], Vs[KT][64];
    for (int k0 = 0; k0 < Sn; k0 += KT) {
        for (int i = tid; i < KT * 64; i += 128) {
            int r = i >> 6, ccol = i & 63;
            size_t src = (size_t)(b * Sn + k0 + r) * Dn + h * DHn + ccol;
            Ks[r][ccol] = k[src];
            Vs[r][ccol] = v[src];
        }
        __syncthreads();
        float sv[KT];
        float smax = -1e30f;
        #pragma unroll
        for (int j = 0; j < KT; j++) {
            float s = 0.f;
            #pragma unroll
            for (int d = 0; d < 64; d++) s += qreg[d] * Ks[j][d];
            sv[j] = s;
            smax = fmaxf(smax, s);
        }
        float mnew = fmaxf(m, smax);
        float alpha = expf(m - mnew);
        float psum = 0.f;
        #pragma unroll
        for (int j = 0; j < KT; j++) { float p = expf(sv[j] - mnew); sv[j] = p; psum += p; }
        lsum = lsum * alpha + psum;
        #pragma unroll
        for (int d = 0; d < 64; d++) {
            float a = 0.f;
            #pragma unroll
            for (int j = 0; j < KT; j++) a += sv[j] * Vs[j][d];
            oacc[d] = oacc[d] * alpha + a;
        }
        m = mnew;
        __syncthreads();
    }
    float inv = 1.0f / lsum;
    float* op = o_out + (size_t)qrow * Dn + h * DHn;
    #pragma unroll
    for (int d = 0; d < 64; d++) op[d] = roundtf(oacc[d] * inv);
}

// ---------------------------------------------------------------------------
// MoE routing (reads EXACT h2 + exact gate_w: selection identical to reference)
// ---------------------------------------------------------------------------
__global__ void zero_counts_kernel() {
    if (threadIdx.x < En) g_counts[threadIdx.x] = 0;
}

__global__ void routing_kernel(const float* __restrict__ h2,
                               const float* __restrict__ gate_w,
                               const float* __restrict__ gate_b,
                               const float* __restrict__ bias_e) {
    int t = blockIdx.x;
    int wid = threadIdx.x >> 5, lane = threadIdx.x & 31;
    __shared__ float logit[En];
    float s = 0.f;
    const float* row = h2 + (size_t)t * Dn;
    for (int d = lane; d < Dn; d += 32) s += row[d] * gate_w[d * En + wid];
    #pragma unroll
    for (int o = 16; o; o >>= 1) s += __shfl_down_sync(0xffffffffu, s, o);
    if (lane == 0) logit[wid] = s + gate_b[wid];   // TAU = 1
    __syncthreads();
    if (threadIdx.x == 0) {
        float sel[En];
        #pragma unroll
        for (int e = 0; e < En; e++) sel[e] = logit[e] + bias_e[e];
        int i0 = 0;
        #pragma unroll
        for (int e = 1; e < En; e++) if (sel[e] > sel[i0]) i0 = e;
        int i1 = (i0 == 0) ? 1 : 0;
        #pragma unroll
        for (int e = 0; e < En; e++) if (e != i0 && sel[e] > sel[i1]) i1 = e;
        float l0 = logit[i0], l1 = logit[i1];
        float mm = fmaxf(l0, l1);
        float e0 = expf(l0 - mm), e1 = expf(l1 - mm);
        float inv = 1.0f / (e0 + e1);
        g_idx[t * 2] = i0;     g_idx[t * 2 + 1] = i1;
        g_gate[t * 2] = e0 * inv; g_gate[t * 2 + 1] = e1 * inv;
        g_pos[t * 2]     = atomicAdd(&g_counts[i0], 1);
        g_pos[t * 2 + 1] = atomicAdd(&g_counts[i1], 1);
    }
}

__global__ void offsets_kernel() {
    if (threadIdx.x == 0) {
        int acc = 0;
        for (int e = 0; e < En; e++) { g_offsets[e] = acc; acc += g_counts[e]; }
    }
}

__global__ void fill_slots_kernel() {
    int t = blockIdx.x * 256 + threadIdx.x;
    if (t >= Tn) return;
    #pragma unroll
    for (int kk = 0; kk < 2; kk++) {
        int e = g_idx[t * 2 + kk];
        int slot = g_offsets[e] + g_pos[t * 2 + kk];
        g_slotof[t * 2 + kk] = slot;
        g_slot2tok[slot] = t;
    }
}

// ---------------------------------------------------------------------------
// Final combine: out = x1 + g0*eout[slot0] + g1*eout[slot1]
// ---------------------------------------------------------------------------
__global__ void combine_kernel(const float* __restrict__ x1, float* __restrict__ out) {
    int t = blockIdx.x;
    int d = blockIdx.y * 256 + threadIdx.x;
    int s0 = g_slotof[t * 2], s1 = g_slotof[t * 2 + 1];
    float g0 = g_gate[t * 2], g1 = g_gate[t * 2 + 1];
    out[(size_t)t * Dn + d] = x1[(size_t)t * Dn + d]
                            + g0 * g_eout[(size_t)s0 * Dn + d]
                            + g1 * g_eout[(size_t)s1 * Dn + d];
}

// ---------------------------------------------------------------------------
// launch
// ---------------------------------------------------------------------------
extern "C" void kernel_launch(void* const* d_in, const int* in_sizes, int n_in,
                              void* d_out, int out_size) {
    const float* x      = (const float*)d_in[0];
    const float* wq     = (const float*)d_in[1];
    const float* wk     = (const float*)d_in[2];
    const float* wv     = (const float*)d_in[3];
    const float* wo     = (const float*)d_in[4];
    const float* ln1_g  = (const float*)d_in[5];
    const float* ln1_b  = (const float*)d_in[6];
    const float* ln2_g  = (const float*)d_in[7];
    const float* ln2_b  = (const float*)d_in[8];
    const float* gate_w = (const float*)d_in[9];
    const float* gate_b = (const float*)d_in[10];
    const float* bias_e = (const float*)d_in[11];
    const float* w1     = (const float*)d_in[12];
    const float* b1     = (const float*)d_in[13];
    const float* w2     = (const float*)d_in[14];
    const float* b2     = (const float*)d_in[15];
    float* out = (float*)d_out;

    float *h1, *qb, *kb, *vb, *att, *x1, *h2x, *eoutp;
    __half *h2h, *midh, *w1h, *w2h;
    cudaGetSymbolAddress((void**)&h1,  g_h1);
    cudaGetSymbolAddress((void**)&qb,  g_q);
    cudaGetSymbolAddress((void**)&kb,  g_k);
    cudaGetSymbolAddress((void**)&vb,  g_v);
    cudaGetSymbolAddress((void**)&att, g_att);
    cudaGetSymbolAddress((void**)&x1,  g_x1);
    cudaGetSymbolAddress((void**)&h2x, g_h2x);
    cudaGetSymbolAddress((void**)&h2h, g_h2h);
    cudaGetSymbolAddress((void**)&midh, g_midh);
    cudaGetSymbolAddress((void**)&w1h, g_w1h);
    cudaGetSymbolAddress((void**)&w2h, g_w2h);
    cudaGetSymbolAddress((void**)&eoutp, g_eout);

    static int smem_set = 0;
    if (!smem_set) {
        cudaFuncSetAttribute(qkv_gemm,   cudaFuncAttributeMaxDynamicSharedMemorySize, SMEM_SZ);
        cudaFuncSetAttribute(oproj_gemm, cudaFuncAttributeMaxDynamicSharedMemorySize, SMEM_SZ);
        cudaFuncSetAttribute(moe_ffn_h,  cudaFuncAttributeMaxDynamicSharedMemorySize, FF_SMEM);
        smem_set = 1;
    }

    // --- weight prep ---
    const int DD4 = Dn * Dn / 4;
    round_small<<<dim3(DD4 / 256, 4), 256>>>(wq, wk, wv, wo);
    transpose_h<<<dim3(Fn / 32, Dn / 32, En), dim3(32, 8)>>>(w1, w1h, Dn, Fn);
    transpose_h<<<dim3(Dn / 32, Fn / 32, En), dim3(32, 8)>>>(w2, w2h, Fn, Dn);

    // --- attention block ---
    ln_kernel<<<Tn, 256>>>(x, ln1_g, ln1_b, h1, nullptr, nullptr);
    qkv_gemm<<<dim3(Tn / BM, Dn / BN, 3), 256, SMEM_SZ>>>(h1);
    attn_kernel<<<dim3(Sn / 128, Hn, Bsz), 128>>>(qb, kb, vb, att);
    oproj_gemm<<<dim3(Tn / BM, Dn / BN), 256, SMEM_SZ>>>(x);

    // --- MoE block ---
    ln_kernel<<<Tn, 256>>>(x1, ln2_g, ln2_b, nullptr, h2x, h2h);
    zero_counts_kernel<<<1, 32>>>();
    routing_kernel<<<Tn, 256>>>(h2x, gate_w, gate_b, bias_e);
    offsets_kernel<<<1, 32>>>();
    fill_slots_kernel<<<Tn / 256, 256>>>();
    moe_ffn_h<<<dim3(Tn / BM, Fn / BN, En), 256, FF_SMEM>>>(
        h2h, w1h, b1, midh, nullptr, Dn, Fn, 1);
    moe_ffn_h<<<dim3(Tn / BM, Dn / BN, En), 256, FF_SMEM>>>(
        midh, w2h, b2, nullptr, eoutp, Fn, Dn, 0);
    combine_kernel<<<dim3(Tn, Dn / 256), 256>>>(x1, out);
}